// round 11
// baseline (speedup 1.0000x reference)
#include <cuda_runtime.h>

typedef unsigned long long u64;
typedef unsigned int u32;

#define VOCAB   65
#define SQRT_C  5.656854249492381f   // faithful bug: scores MULTIPLIED by sqrt(32)

// ---------------- scratch (device globals; no allocations allowed) ----------
__device__ __align__(16) float g_Qtab[520 * 32];
__device__ __align__(16) float g_Ktab[520 * 32];   // pre-scaled by SQRT_C
__device__ __align__(16) float g_Vtab[520 * 32];
__device__ float    g_loss;
__device__ unsigned g_done;

// ---------------- packed weights: one constant block, one memcpy ------------
#define WLM_STRIDE 68          // padded vocab row stride (16B-aligned rows)
#define OFF_WMLP   0           // [c][c2] 1024
#define OFF_BMLP   1024        // 32
#define OFF_BLM    1056        // 68 (65 + zero pad)
#define OFF_WLM    1124        // [c][v] 32*68 = 2176
#define PACK_N     3300
__device__   __align__(16) float g_pack[PACK_N];
__constant__ __align__(16) float c_all[PACK_N];

// smem tile of lm-head weights for vocab 0..31 (+ v64 at col 32): [c][36]
#define WS_STRIDE 36
#define WS_N      (32 * WS_STRIDE)

// ---------------- packed f32x2 helpers (sm_103a) ----------------------------
__device__ __forceinline__ u64 fma2(u64 a, u64 b, u64 c) {
    u64 d; asm("fma.rn.f32x2 %0, %1, %2, %3;" : "=l"(d) : "l"(a), "l"(b), "l"(c)); return d;
}
__device__ __forceinline__ u64 add2(u64 a, u64 b) {
    u64 d; asm("add.rn.f32x2 %0, %1, %2;" : "=l"(d) : "l"(a), "l"(b)); return d;
}
__device__ __forceinline__ float hadd2(u64 a) {
    float lo, hi; asm("mov.b64 {%0,%1}, %2;" : "=f"(lo), "=f"(hi) : "l"(a)); return lo + hi;
}
__device__ __forceinline__ u64 pack2(float lo, float hi) {
    u64 r; asm("mov.b64 %0, {%1,%2};" : "=l"(r) : "f"(lo), "f"(hi)); return r;
}
__device__ __forceinline__ float lo2(u64 a) {
    float lo, hi; asm("mov.b64 {%0,%1}, %2;" : "=f"(lo), "=f"(hi) : "l"(a)); return lo;
}
__device__ __forceinline__ float hi2(u64 a) {
    float lo, hi; asm("mov.b64 {%0,%1}, %2;" : "=f"(lo), "=f"(hi) : "l"(a)); return hi;
}
__device__ __forceinline__ ulonglong2 ldc4(const float* p) {
    return *reinterpret_cast<const ulonglong2*>(p);
}

// Precompute Q/K/V tables AND pack weights for the single constant upload.
__global__ void k_tables(const float* __restrict__ tok_emb,
                         const float* __restrict__ pos_emb,
                         const float* __restrict__ Wq,
                         const float* __restrict__ Wk,
                         const float* __restrict__ Wv,
                         const float* __restrict__ Wmlp,
                         const float* __restrict__ bmlp,
                         const float* __restrict__ Wlm,
                         const float* __restrict__ blm) {
    int i = blockIdx.x * blockDim.x + threadIdx.x;
    if (i == 0) { g_loss = 0.0f; g_done = 0u; }
    if (i < 520 * 32) {
        int row = i >> 5, c = i & 31;
        int t = row / 65, tok = row % 65;
        int h = c >> 3, d = c & 7;
        float aq = 0.f, ak = 0.f, av = 0.f;
#pragma unroll
        for (int cc = 0; cc < 32; cc++) {
            float xv = tok_emb[tok * 32 + cc] + pos_emb[t * 32 + cc];
            int wi = h * 256 + cc * 8 + d;
            aq = fmaf(xv, Wq[wi], aq);
            ak = fmaf(xv, Wk[wi], ak);
            av = fmaf(xv, Wv[wi], av);
        }
        g_Qtab[i] = aq;
        g_Ktab[i] = ak * SQRT_C;
        g_Vtab[i] = av;
    } else {
        int i2 = i - 520 * 32;
        if (i2 < PACK_N) {
            float v;
            if (i2 < OFF_BMLP)      v = Wmlp[i2];
            else if (i2 < OFF_BLM)  v = bmlp[i2 - OFF_BMLP];
            else if (i2 < OFF_WLM) {
                int j = i2 - OFF_BLM;
                v = (j < 65) ? blm[j] : 0.0f;
            } else {
                int j  = i2 - OFF_WLM;
                int c  = j / WLM_STRIDE;
                int vv = j - c * WLM_STRIDE;
                v = (vv < 65) ? Wlm[c * 65 + vv] : 0.0f;
            }
            g_pack[i2] = v;
        }
    }
}

#define KV_LS_STRIDE 264   // floats per sequence (K/V phase)
#define XCH_STRIDE   36    // exchange row stride: lane bank offset 4 -> conflict-free
#define YBUF_OFF     4608  // second exchange buffer (after V reads complete)

// Main fused kernel: 256 threads = 128 tokens x 2 halves.
// half 0: heads 0-1, y[0..16), vocab 0..31 (SMEM weights)
// half 1: heads 2-3, y[16..32), vocab 32..64 (CONSTANT weights)
__global__ __launch_bounds__(256, 4)
void k_main(const int* __restrict__ idx, const int* __restrict__ tgt,
            float* __restrict__ out, int write_logits,
            int loss_idx, float inv_n, int nblocks) {
    // phases: K[0..4224) V[4224..8448) -> ovbuf[0..4608) ybuf[4608..9216)
    //         -> logits stage [128][65] dense at [0..8320)
    __shared__ __align__(16) float  s_un[9216];
    __shared__ __align__(16) float  s_wlm2[WS_N];
    __shared__ float2               s_cmb[256];
    __shared__ float                s_lred[8];

    const float* c_wmlp = c_all + OFF_WMLP;
    const float* c_bmlp = c_all + OFF_BMLP;
    const float* c_blm  = c_all + OFF_BLM;
    const float* c_wlm  = c_all + OFF_WLM;

    const int tid  = threadIdx.x;
    const int half = tid >> 7;                 // 0 or 1
    const int tk   = tid & 127;                // token within block
    const int ls   = tk >> 3;
    const int t    = tk & 7;
    const int rowg = blockIdx.x * 128 + tk;
    const int tok  = idx[rowg];
    const int tgtv = tgt[rowg];
    const int qrow = (t * 65 + tok) * 32;

    // stage lm-head smem tile [c][36]: v0..31 + v64 at col 32
    for (int i = tid; i < WS_N; i += 256) {
        int c = i / WS_STRIDE, col = i - c * WS_STRIDE;
        float v = 0.0f;
        if (col < 32)       v = g_pack[OFF_WLM + c * WLM_STRIDE + col];
        else if (col == 32) v = g_pack[OFF_WLM + c * WLM_STRIDE + 64];
        s_wlm2[i] = v;
    }
    // stage K (half 0) / V (half 1) row for own token
    {
        const float4* src = reinterpret_cast<const float4*>(
            (half ? g_Vtab : g_Ktab) + qrow);
        float4* dst = reinterpret_cast<float4*>(
            s_un + half * 4224 + ls * KV_LS_STRIDE + t * 32);
#pragma unroll
        for (int j = 0; j < 8; j++) dst[j] = src[j];
    }
    __syncthreads();

    // ----- attention for OWN head-pair (hp = half) -----
    u64 oacc[8];
    {
        u64 q2[8];
        {
            const ulonglong2* q4 =
                reinterpret_cast<const ulonglong2*>(g_Qtab + qrow + half * 16);
#pragma unroll
            for (int j = 0; j < 4; j++) {
                ulonglong2 a = q4[j];
                q2[2 * j] = a.x; q2[2 * j + 1] = a.y;
            }
        }
        float sc[2][8];
        const float* kb = s_un + ls * KV_LS_STRIDE + half * 16;
#pragma unroll
        for (int s = 0; s < 8; s++) {
            const ulonglong2* kr = reinterpret_cast<const ulonglong2*>(kb + s * 32);
            ulonglong2 a = kr[0], b = kr[1], c = kr[2], d = kr[3];
            u64 e0 = 0ull, e1 = 0ull, f0 = 0ull, f1 = 0ull;
            e0 = fma2(q2[0], a.x, e0); e1 = fma2(q2[1], a.y, e1);
            e0 = fma2(q2[2], b.x, e0); e1 = fma2(q2[3], b.y, e1);
            f0 = fma2(q2[4], c.x, f0); f1 = fma2(q2[5], c.y, f1);
            f0 = fma2(q2[6], d.x, f0); f1 = fma2(q2[7], d.y, f1);
            float se = hadd2(add2(e0, e1));
            float sf = hadd2(add2(f0, f1));
            sc[0][s] = (s <= t) ? se : -1e30f;
            sc[1][s] = (s <= t) ? sf : -1e30f;
        }
        float rinv[2];
#pragma unroll
        for (int hh = 0; hh < 2; hh++) {
            float m01 = fmaxf(sc[hh][0], sc[hh][1]);
            float m23 = fmaxf(sc[hh][2], sc[hh][3]);
            float m45 = fmaxf(sc[hh][4], sc[hh][5]);
            float m67 = fmaxf(sc[hh][6], sc[hh][7]);
            float m = fmaxf(fmaxf(m01, m23), fmaxf(m45, m67));
            float e0 = __expf(sc[hh][0] - m), e1 = __expf(sc[hh][1] - m);
            float e2 = __expf(sc[hh][2] - m), e3 = __expf(sc[hh][3] - m);
            float e4 = __expf(sc[hh][4] - m), e5 = __expf(sc[hh][5] - m);
            float e6 = __expf(sc[hh][6] - m), e7 = __expf(sc[hh][7] - m);
            sc[hh][0] = e0; sc[hh][1] = e1; sc[hh][2] = e2; sc[hh][3] = e3;
            sc[hh][4] = e4; sc[hh][5] = e5; sc[hh][6] = e6; sc[hh][7] = e7;
            float sum = ((e0 + e1) + (e2 + e3)) + ((e4 + e5) + (e6 + e7));
            rinv[hh] = __fdividef(1.0f, sum);
        }
#pragma unroll
        for (int j = 0; j < 8; j++) oacc[j] = 0ull;
        const float* vb = s_un + 4224 + ls * KV_LS_STRIDE + half * 16;
#pragma unroll
        for (int s = 0; s < 8; s++) {
            const ulonglong2* vr = reinterpret_cast<const ulonglong2*>(vb + s * 32);
            ulonglong2 a = vr[0], b = vr[1], c = vr[2], d = vr[3];
            float p0 = sc[0][s] * rinv[0];
            float p1 = sc[1][s] * rinv[1];
            u64 p02 = pack2(p0, p0), p12 = pack2(p1, p1);
            oacc[0] = fma2(p02, a.x, oacc[0]); oacc[1] = fma2(p02, a.y, oacc[1]);
            oacc[2] = fma2(p02, b.x, oacc[2]); oacc[3] = fma2(p02, b.y, oacc[3]);
            oacc[4] = fma2(p12, c.x, oacc[4]); oacc[5] = fma2(p12, c.y, oacc[5]);
            oacc[6] = fma2(p12, d.x, oacc[6]); oacc[7] = fma2(p12, d.y, oacc[7]);
        }
    }
    __syncthreads();   // everyone done reading K/V

    // ----- exchange ov halves (ovbuf overlaps dead K region) -----
    {
        ulonglong2* dst = reinterpret_cast<ulonglong2*>(
            s_un + tk * XCH_STRIDE + half * 16);
#pragma unroll
        for (int j = 0; j < 4; j++) {
            ulonglong2 v; v.x = oacc[2 * j]; v.y = oacc[2 * j + 1];
            dst[j] = v;
        }
    }
    __syncthreads();
    float ov[32];
    {
        const float4* src = reinterpret_cast<const float4*>(s_un + tk * XCH_STRIDE);
#pragma unroll
        for (int j = 0; j < 8; j++) {
            float4 a = src[j];
            ov[4 * j] = a.x; ov[4 * j + 1] = a.y;
            ov[4 * j + 2] = a.z; ov[4 * j + 3] = a.w;
        }
    }

    // ----- MLP: own 16 outputs (c2 in [half*16, half*16+16)); CONSTANT port --
    u64 macc[8];
#pragma unroll
    for (int p = 0; p < 4; p++) {
        ulonglong2 b = ldc4(c_bmlp + half * 16 + 4 * p);
        macc[2 * p] = b.x; macc[2 * p + 1] = b.y;
    }
#pragma unroll
    for (int c = 0; c < 32; c++) {
        u64 xb = pack2(ov[c], ov[c]);
        const float* wr = c_wmlp + c * 32 + half * 16;
#pragma unroll
        for (int q = 0; q < 4; q++) {
            ulonglong2 w = ldc4(wr + 4 * q);
            macc[2 * q]     = fma2(xb, w.x, macc[2 * q]);
            macc[2 * q + 1] = fma2(xb, w.y, macc[2 * q + 1]);
        }
    }
    // relu + exchange y halves (ybuf disjoint from ovbuf)
    {
        ulonglong2* dst = reinterpret_cast<ulonglong2*>(
            s_un + YBUF_OFF + tk * XCH_STRIDE + half * 16);
#pragma unroll
        for (int j = 0; j < 4; j++) {
            ulonglong2 v;
            v.x = pack2(fmaxf(lo2(macc[2 * j]), 0.f),     fmaxf(hi2(macc[2 * j]), 0.f));
            v.y = pack2(fmaxf(lo2(macc[2 * j + 1]), 0.f), fmaxf(hi2(macc[2 * j + 1]), 0.f));
            dst[j] = v;
        }
    }
    __syncthreads();
    float y[32];
    {
        const float4* src = reinterpret_cast<const float4*>(
            s_un + YBUF_OFF + tk * XCH_STRIDE);
#pragma unroll
        for (int j = 0; j < 8; j++) {
            float4 a = src[j];
            y[4 * j] = a.x; y[4 * j + 1] = a.y;
            y[4 * j + 2] = a.z; y[4 * j + 3] = a.w;
        }
    }
    __syncthreads();   // y loads done -> stage region may be overwritten

    // ----- lm-head: own 32/33 logits; online LSE with tree reductions -----
    float* stagerow = s_un + tk * 65;
    float m = -1e30f, sum = 0.f;

#define LM_CHUNK(VB, WPTR_EXPR)                                               \
    {                                                                         \
        const int vb = (VB);                                                  \
        u64 acc[8];                                                           \
        _Pragma("unroll")                                                     \
        for (int p = 0; p < 4; p++) {                                         \
            ulonglong2 b = ldc4(c_blm + vb + 4 * p);                          \
            acc[2 * p] = b.x; acc[2 * p + 1] = b.y;                           \
        }                                                                     \
        _Pragma("unroll")                                                     \
        for (int c = 0; c < 32; c++) {                                        \
            u64 yb = pack2(y[c], y[c]);                                       \
            const float* wr = (WPTR_EXPR);                                    \
            _Pragma("unroll")                                                 \
            for (int q = 0; q < 4; q++) {                                     \
                ulonglong2 w = *reinterpret_cast<const ulonglong2*>(wr + 4 * q); \
                acc[2 * q]     = fma2(yb, w.x, acc[2 * q]);                   \
                acc[2 * q + 1] = fma2(yb, w.y, acc[2 * q + 1]);               \
            }                                                                 \
        }                                                                     \
        float l[16];                                                          \
        _Pragma("unroll")                                                     \
        for (int p = 0; p < 8; p++) {                                         \
            l[2 * p] = lo2(acc[p]); l[2 * p + 1] = hi2(acc[p]);               \
            stagerow[vb + 2 * p]     = l[2 * p];                              \
            stagerow[vb + 2 * p + 1] = l[2 * p + 1];                          \
        }                                                                     \
        float t0 = fmaxf(l[0], l[1]),  t1 = fmaxf(l[2], l[3]);                \
        float t2 = fmaxf(l[4], l[5]),  t3 = fmaxf(l[6], l[7]);                \
        float t4 = fmaxf(l[8], l[9]),  t5 = fmaxf(l[10], l[11]);              \
        float t6 = fmaxf(l[12], l[13]), t7 = fmaxf(l[14], l[15]);             \
        float cm = fmaxf(fmaxf(fmaxf(t0, t1), fmaxf(t2, t3)),                 \
                         fmaxf(fmaxf(t4, t5), fmaxf(t6, t7)));                \
        float mn = fmaxf(m, cm);                                              \
        float e[16];                                                          \
        _Pragma("unroll")                                                     \
        for (int p = 0; p < 16; p++) e[p] = __expf(l[p] - mn);                \
        float s0 = ((e[0] + e[1]) + (e[2] + e[3])) + ((e[4] + e[5]) + (e[6] + e[7])); \
        float s1 = ((e[8] + e[9]) + (e[10] + e[11])) + ((e[12] + e[13]) + (e[14] + e[15])); \
        sum = sum * __expf(m - mn) + (s0 + s1);                               \
        m = mn;                                                               \
    }

    if (half == 0) {        // v0..31 from SMEM tile
        LM_CHUNK(0,  s_wlm2 + c * WS_STRIDE + 0)
        LM_CHUNK(16, s_wlm2 + c * WS_STRIDE + 16)
    } else {                // v32..63 from CONSTANT; v64 from SMEM col 32
        LM_CHUNK(32, c_wlm + c * WLM_STRIDE + 32)
        LM_CHUNK(48, c_wlm + c * WLM_STRIDE + 48)
        u64 acc = *reinterpret_cast<const u64*>(c_blm + 64);
#pragma unroll
        for (int c = 0; c < 32; c++) {
            u64 yb = pack2(y[c], y[c]);
            u64 w = *reinterpret_cast<const u64*>(s_wlm2 + c * WS_STRIDE + 32);
            acc = fma2(yb, w, acc);
        }
        float l64 = lo2(acc);
        stagerow[64] = l64;
        float mn = fmaxf(m, l64);
        sum = sum * __expf(m - mn) + __expf(l64 - mn);
        m = mn;
    }
#undef LM_CHUNK

    // ----- combine LSE across halves; loss by half 0 -----
    s_cmb[tid] = make_float2(m, sum);
    __syncthreads();       // also: stage rows complete for ltgt read + flush

    float lossi = 0.f;
    if (half == 0) {
        float2 c0 = s_cmb[tid];
        float2 c1 = s_cmb[tid + 128];
        float mm = fmaxf(c0.x, c1.x);
        float ss = c0.y * __expf(c0.x - mm) + c1.y * __expf(c1.x - mm);
        lossi = (mm + __logf(ss)) - stagerow[tgtv];
    }
#pragma unroll
    for (int off = 16; off > 0; off >>= 1)
        lossi += __shfl_down_sync(0xffffffffu, lossi, off);
    if ((tid & 31) == 0) s_lred[tid >> 5] = lossi;
    __syncthreads();
    if (tid == 0) {
        float acc = 0.f;
#pragma unroll
        for (int w = 0; w < 8; w++) acc += s_lred[w];
        atomicAdd(&g_loss, acc);
        __threadfence();
        unsigned prev = atomicAdd(&g_done, 1u);
        if ((int)prev == nblocks - 1 && loss_idx >= 0)
            out[loss_idx] = g_loss * inv_n;
    }

    // ----- single TMA bulk store: SMEM stage -> GMEM logits (33280 B) -----
    if (write_logits && tid == 0) {
        u32 saddr;
        asm("{ .reg .u64 tmp; cvta.to.shared.u64 tmp, %1; cvt.u32.u64 %0, tmp; }"
            : "=r"(saddr) : "l"(s_un));
        const float* gdst = out + (size_t)blockIdx.x * 8320;
        asm volatile("fence.proxy.async.shared::cta;" ::: "memory");
        asm volatile("cp.async.bulk.global.shared::cta.bulk_group [%0], [%1], %2;"
                     :: "l"(gdst), "r"(saddr), "r"(33280) : "memory");
        asm volatile("cp.async.bulk.commit_group;" ::: "memory");
        asm volatile("cp.async.bulk.wait_group.read 0;" ::: "memory");
    }
}

extern "C" void kernel_launch(void* const* d_in, const int* in_sizes, int n_in,
                              void* d_out, int out_size) {
    const int*   idx     = (const int*)d_in[0];
    const int*   targets = (const int*)d_in[1];
    const float* tok_emb = (const float*)d_in[2];
    const float* pos_emb = (const float*)d_in[3];
    const float* Wq      = (const float*)d_in[4];
    const float* Wk      = (const float*)d_in[5];
    const float* Wv      = (const float*)d_in[6];
    const float* Wmlp    = (const float*)d_in[7];
    const float* bmlp    = (const float*)d_in[8];
    const float* Wlm     = (const float*)d_in[9];
    const float* blm     = (const float*)d_in[10];
    float* out = (float*)d_out;

    const long nrows = in_sizes[0];           // B*T = 524288
    const long total = nrows * VOCAB;
    int write_logits = ((long)out_size >= total) ? 1 : 0;
    int loss_idx = -1;
    if ((long)out_size == total + 1) loss_idx = (int)total;
    else if (out_size == 1)          { loss_idx = 0; write_logits = 0; }

    int work = 520 * 32 + PACK_N;
    k_tables<<<(work + 255) / 256, 256>>>(tok_emb, pos_emb, Wq, Wk, Wv,
                                          Wmlp, bmlp, Wlm, blm);
    {
        void* src = nullptr;
        cudaGetSymbolAddress(&src, g_pack);
        cudaMemcpyToSymbolAsync(c_all, src, PACK_N * sizeof(float), 0,
                                cudaMemcpyDeviceToDevice);
    }

    int nblocks = (int)(nrows / 128);
    k_main<<<nblocks, 256>>>(idx, targets, out, write_logits, loss_idx,
                             1.0f / (float)nrows, nblocks);
}

// round 12
// speedup vs baseline: 1.2082x; 1.2082x over previous
#include <cuda_runtime.h>

typedef unsigned long long u64;
typedef unsigned int u32;

#define VOCAB   65
#define SQRT_C  5.656854249492381f   // faithful bug: scores MULTIPLIED by sqrt(32)

// ---------------- scratch (device globals; no allocations allowed) ----------
__device__ __align__(16) float g_Qtab[520 * 32];
__device__ __align__(16) float g_Ktab[520 * 32];   // pre-scaled by SQRT_C
__device__ __align__(16) float g_Vtab[520 * 32];
__device__ float    g_loss;
__device__ unsigned g_done;

// ---------------- packed weights: one constant block, one memcpy ------------
#define WLM_STRIDE 68          // padded vocab row stride in g_pack
#define OFF_WMLP   0           // [c][c2] 1024
#define OFF_BMLP   1024        // 32
#define OFF_BLM    1056        // 68 (65 + zero pad)
#define OFF_WLM    1124        // [c][v] 32*68 = 2176
#define PACK_N     3300
__device__   __align__(16) float g_pack[PACK_N];
__constant__ __align__(16) float c_all[PACK_N];    // MLP + biases read from here

// ---------------- packed f32x2 helpers (sm_103a) ----------------------------
__device__ __forceinline__ u64 fma2(u64 a, u64 b, u64 c) {
    u64 d; asm("fma.rn.f32x2 %0, %1, %2, %3;" : "=l"(d) : "l"(a), "l"(b), "l"(c)); return d;
}
__device__ __forceinline__ u64 add2(u64 a, u64 b) {
    u64 d; asm("add.rn.f32x2 %0, %1, %2;" : "=l"(d) : "l"(a), "l"(b)); return d;
}
__device__ __forceinline__ float hadd2(u64 a) {
    float lo, hi; asm("mov.b64 {%0,%1}, %2;" : "=f"(lo), "=f"(hi) : "l"(a)); return lo + hi;
}
__device__ __forceinline__ u64 pack2(float lo, float hi) {
    u64 r; asm("mov.b64 %0, {%1,%2};" : "=l"(r) : "f"(lo), "f"(hi)); return r;
}
__device__ __forceinline__ float lo2(u64 a) {
    float lo, hi; asm("mov.b64 {%0,%1}, %2;" : "=f"(lo), "=f"(hi) : "l"(a)); return lo;
}
__device__ __forceinline__ float hi2(u64 a) {
    float lo, hi; asm("mov.b64 {%0,%1}, %2;" : "=f"(lo), "=f"(hi) : "l"(a)); return hi;
}
__device__ __forceinline__ ulonglong2 ldc4(const float* p) {
    return *reinterpret_cast<const ulonglong2*>(p);
}

// Precompute Q/K/V tables AND pack weights for the single constant upload.
__global__ void k_tables(const float* __restrict__ tok_emb,
                         const float* __restrict__ pos_emb,
                         const float* __restrict__ Wq,
                         const float* __restrict__ Wk,
                         const float* __restrict__ Wv,
                         const float* __restrict__ Wmlp,
                         const float* __restrict__ bmlp,
                         const float* __restrict__ Wlm,
                         const float* __restrict__ blm) {
    int i = blockIdx.x * blockDim.x + threadIdx.x;
    if (i == 0) { g_loss = 0.0f; g_done = 0u; }
    if (i < 520 * 32) {
        int row = i >> 5, c = i & 31;
        int t = row / 65, tok = row % 65;
        int h = c >> 3, d = c & 7;
        float aq = 0.f, ak = 0.f, av = 0.f;
#pragma unroll
        for (int cc = 0; cc < 32; cc++) {
            float xv = tok_emb[tok * 32 + cc] + pos_emb[t * 32 + cc];
            int wi = h * 256 + cc * 8 + d;
            aq = fmaf(xv, Wq[wi], aq);
            ak = fmaf(xv, Wk[wi], ak);
            av = fmaf(xv, Wv[wi], av);
        }
        g_Qtab[i] = aq;
        g_Ktab[i] = ak * SQRT_C;
        g_Vtab[i] = av;
    } else {
        int i2 = i - 520 * 32;
        if (i2 < PACK_N) {
            float v;
            if (i2 < OFF_BMLP)      v = Wmlp[i2];
            else if (i2 < OFF_BLM)  v = bmlp[i2 - OFF_BMLP];
            else if (i2 < OFF_WLM) {
                int j = i2 - OFF_BLM;
                v = (j < 65) ? blm[j] : 0.0f;
            } else {
                int j  = i2 - OFF_WLM;
                int c  = j / WLM_STRIDE;
                int vv = j - c * WLM_STRIDE;
                v = (vv < 65) ? Wlm[c * 65 + vv] : 0.0f;
            }
            g_pack[i2] = v;
        }
    }
}

#define KV_LS_STRIDE 264   // floats per sequence (K/V phase)
#define YT_STRIDE    132   // yT row stride (floats)
#define WV_REGION    520   // 32*16 + 8 pad -> regions start on banks 0,8,16,24

// Main fused kernel: 128 threads. Attention+MLP: thread = token.
// lm-head: thread = (token-group tid>>2, vocab-chunk tid&3); 4 tokens x 16 vocab tile.
__global__ __launch_bounds__(128, 4)
void k_main(const int* __restrict__ idx, const int* __restrict__ tgt,
            float* __restrict__ out, int write_logits,
            int loss_idx, float inv_n, int nblocks) {
    // s_un: K[0..4224) V[4224..8448) -> yT[0..4224) -> logits stage [128][65]
    __shared__ __align__(16) float  s_un[8448];
    __shared__ __align__(16) float  s_wv[4 * WV_REGION];  // Wlm tiles per chunk
    __shared__ __align__(16) float  s_w64[32];            // Wlm column v=64
    __shared__ __align__(8)  float2 s_part[128 * 5];      // per-token LSE partials
    __shared__ float                s_lred[4];

    const float* c_wmlp = c_all + OFF_WMLP;
    const float* c_bmlp = c_all + OFF_BMLP;
    const float* c_blm  = c_all + OFF_BLM;

    const int tid  = threadIdx.x;
    const int ls   = tid >> 3;
    const int t    = tid & 7;
    const int rowg = blockIdx.x * 128 + tid;
    const int tok  = idx[rowg];
    const int tgtv = tgt[rowg];
    const int qrow = (t * 65 + tok) * 32;

    // stage lm-head weight tiles: region r holds W[c][16r..16r+16) as [c][16]
    for (int i = tid; i < 4 * WV_REGION; i += 128) {
        int r = i / WV_REGION, j = i - r * WV_REGION;
        float v = 0.0f;
        if (j < 512) {
            int c = j >> 4, vx = j & 15;
            v = g_pack[OFF_WLM + c * WLM_STRIDE + r * 16 + vx];
        }
        s_wv[i] = v;
    }
    if (tid < 32) s_w64[tid] = g_pack[OFF_WLM + tid * WLM_STRIDE + 64];

    // k, v rows into shared (own row; padded ls stride)
    {
        const float4* k4 = reinterpret_cast<const float4*>(g_Ktab + qrow);
        const float4* v4 = reinterpret_cast<const float4*>(g_Vtab + qrow);
        float4* skd = reinterpret_cast<float4*>(s_un + ls * KV_LS_STRIDE + t * 32);
        float4* svd = reinterpret_cast<float4*>(s_un + 4224 + ls * KV_LS_STRIDE + t * 32);
#pragma unroll
        for (int j = 0; j < 8; j++) { skd[j] = k4[j]; svd[j] = v4[j]; }
    }
    __syncthreads();

    // ----- attention in head-pairs (R7 structure) -----
    float ov[32];
#pragma unroll
    for (int hp = 0; hp < 2; hp++) {
        u64 q2[8];
        {
            const ulonglong2* q4 =
                reinterpret_cast<const ulonglong2*>(g_Qtab + qrow + hp * 16);
#pragma unroll
            for (int j = 0; j < 4; j++) {
                ulonglong2 a = q4[j];
                q2[2 * j] = a.x; q2[2 * j + 1] = a.y;
            }
        }
        float sc[2][8];
        const float* kb = s_un + ls * KV_LS_STRIDE + hp * 16;
#pragma unroll
        for (int s = 0; s < 8; s++) {
            const ulonglong2* kr = reinterpret_cast<const ulonglong2*>(kb + s * 32);
            ulonglong2 a = kr[0], b = kr[1], c = kr[2], d = kr[3];
            u64 e0 = 0ull, e1 = 0ull, f0 = 0ull, f1 = 0ull;
            e0 = fma2(q2[0], a.x, e0); e1 = fma2(q2[1], a.y, e1);
            e0 = fma2(q2[2], b.x, e0); e1 = fma2(q2[3], b.y, e1);
            f0 = fma2(q2[4], c.x, f0); f1 = fma2(q2[5], c.y, f1);
            f0 = fma2(q2[6], d.x, f0); f1 = fma2(q2[7], d.y, f1);
            float se = hadd2(add2(e0, e1));
            float sf = hadd2(add2(f0, f1));
            sc[0][s] = (s <= t) ? se : -1e30f;
            sc[1][s] = (s <= t) ? sf : -1e30f;
        }
        float rinv[2];
#pragma unroll
        for (int hh = 0; hh < 2; hh++) {
            float m01 = fmaxf(sc[hh][0], sc[hh][1]);
            float m23 = fmaxf(sc[hh][2], sc[hh][3]);
            float m45 = fmaxf(sc[hh][4], sc[hh][5]);
            float m67 = fmaxf(sc[hh][6], sc[hh][7]);
            float m = fmaxf(fmaxf(m01, m23), fmaxf(m45, m67));
            float sum = 0.f;
#pragma unroll
            for (int s = 0; s < 8; s++) {
                float e = __expf(sc[hh][s] - m);
                sc[hh][s] = e;
                sum += e;
            }
            rinv[hh] = __fdividef(1.0f, sum);
        }
        u64 oacc[8];
#pragma unroll
        for (int j = 0; j < 8; j++) oacc[j] = 0ull;
        const float* vb = s_un + 4224 + ls * KV_LS_STRIDE + hp * 16;
#pragma unroll
        for (int s = 0; s < 8; s++) {
            const ulonglong2* vr = reinterpret_cast<const ulonglong2*>(vb + s * 32);
            ulonglong2 a = vr[0], b = vr[1], c = vr[2], d = vr[3];
            float p0 = sc[0][s] * rinv[0];
            float p1 = sc[1][s] * rinv[1];
            u64 p02 = pack2(p0, p0), p12 = pack2(p1, p1);
            oacc[0] = fma2(p02, a.x, oacc[0]); oacc[1] = fma2(p02, a.y, oacc[1]);
            oacc[2] = fma2(p02, b.x, oacc[2]); oacc[3] = fma2(p02, b.y, oacc[3]);
            oacc[4] = fma2(p12, c.x, oacc[4]); oacc[5] = fma2(p12, c.y, oacc[5]);
            oacc[6] = fma2(p12, d.x, oacc[6]); oacc[7] = fma2(p12, d.y, oacc[7]);
        }
#pragma unroll
        for (int j = 0; j < 8; j++) {
            ov[hp * 16 + 2 * j]     = lo2(oacc[j]);
            ov[hp * 16 + 2 * j + 1] = hi2(oacc[j]);
        }
    }
    __syncthreads();   // done reading K/V

    // ----- MLP (CONSTANT port), then write y transposed into dead K region --
    {
        u64 macc[16];
#pragma unroll
        for (int j = 0; j < 8; j++) {
            ulonglong2 b = ldc4(c_bmlp + 4 * j);
            macc[2 * j] = b.x; macc[2 * j + 1] = b.y;
        }
#pragma unroll
        for (int c = 0; c < 32; c++) {
            u64 xb = pack2(ov[c], ov[c]);
#pragma unroll
            for (int jj = 0; jj < 8; jj++) {
                ulonglong2 w = ldc4(c_wmlp + c * 32 + 4 * jj);
                macc[2 * jj]     = fma2(xb, w.x, macc[2 * jj]);
                macc[2 * jj + 1] = fma2(xb, w.y, macc[2 * jj + 1]);
            }
        }
        // yT[c][tok] = relu(...); conflict-free STS.32 per c
#pragma unroll
        for (int j = 0; j < 16; j++) {
            s_un[(2 * j)     * YT_STRIDE + tid] = fmaxf(lo2(macc[j]), 0.f);
            s_un[(2 * j + 1) * YT_STRIDE + tid] = fmaxf(hi2(macc[j]), 0.f);
        }
    }
    __syncthreads();

    // ----- lm-head: thread tile = [4 tokens] x [16 vocab] -----
    const int grp = tid >> 2;          // token group: tokens 4g..4g+3
    const int chk = tid & 3;           // vocab chunk: v in [16chk, 16chk+16)
    const int tb  = grp * 4;
    const int vb  = chk * 16;

    u64 acc[4][8];
    {
        u64 b0, b1, b2, b3, b4, b5, b6, b7;
        ulonglong2 ba = ldc4(c_blm + vb), bb = ldc4(c_blm + vb + 4);
        ulonglong2 bc = ldc4(c_blm + vb + 8), bd = ldc4(c_blm + vb + 12);
        b0 = ba.x; b1 = ba.y; b2 = bb.x; b3 = bb.y;
        b4 = bc.x; b5 = bc.y; b6 = bd.x; b7 = bd.y;
#pragma unroll
        for (int tt = 0; tt < 4; tt++) {
            acc[tt][0] = b0; acc[tt][1] = b1; acc[tt][2] = b2; acc[tt][3] = b3;
            acc[tt][4] = b4; acc[tt][5] = b5; acc[tt][6] = b6; acc[tt][7] = b7;
        }
    }
    u64 acc64a = 0ull, acc64b = 0ull;      // v=64 (chunk 0 only)
    const float* wvb = s_wv + chk * WV_REGION;
#pragma unroll
    for (int c = 0; c < 32; c++) {
        float4 yv = *reinterpret_cast<const float4*>(s_un + c * YT_STRIDE + tb);
        const ulonglong2* wr = reinterpret_cast<const ulonglong2*>(wvb + c * 16);
        ulonglong2 wa = wr[0], wc = wr[1], we = wr[2], wg = wr[3];
        u64 y0 = pack2(yv.x, yv.x), y1 = pack2(yv.y, yv.y);
        u64 y2 = pack2(yv.z, yv.z), y3 = pack2(yv.w, yv.w);
        acc[0][0] = fma2(y0, wa.x, acc[0][0]); acc[0][1] = fma2(y0, wa.y, acc[0][1]);
        acc[0][2] = fma2(y0, wc.x, acc[0][2]); acc[0][3] = fma2(y0, wc.y, acc[0][3]);
        acc[0][4] = fma2(y0, we.x, acc[0][4]); acc[0][5] = fma2(y0, we.y, acc[0][5]);
        acc[0][6] = fma2(y0, wg.x, acc[0][6]); acc[0][7] = fma2(y0, wg.y, acc[0][7]);
        acc[1][0] = fma2(y1, wa.x, acc[1][0]); acc[1][1] = fma2(y1, wa.y, acc[1][1]);
        acc[1][2] = fma2(y1, wc.x, acc[1][2]); acc[1][3] = fma2(y1, wc.y, acc[1][3]);
        acc[1][4] = fma2(y1, we.x, acc[1][4]); acc[1][5] = fma2(y1, we.y, acc[1][5]);
        acc[1][6] = fma2(y1, wg.x, acc[1][6]); acc[1][7] = fma2(y1, wg.y, acc[1][7]);
        acc[2][0] = fma2(y2, wa.x, acc[2][0]); acc[2][1] = fma2(y2, wa.y, acc[2][1]);
        acc[2][2] = fma2(y2, wc.x, acc[2][2]); acc[2][3] = fma2(y2, wc.y, acc[2][3]);
        acc[2][4] = fma2(y2, we.x, acc[2][4]); acc[2][5] = fma2(y2, we.y, acc[2][5]);
        acc[2][6] = fma2(y2, wg.x, acc[2][6]); acc[2][7] = fma2(y2, wg.y, acc[2][7]);
        acc[3][0] = fma2(y3, wa.x, acc[3][0]); acc[3][1] = fma2(y3, wa.y, acc[3][1]);
        acc[3][2] = fma2(y3, wc.x, acc[3][2]); acc[3][3] = fma2(y3, wc.y, acc[3][3]);
        acc[3][4] = fma2(y3, we.x, acc[3][4]); acc[3][5] = fma2(y3, we.y, acc[3][5]);
        acc[3][6] = fma2(y3, wg.x, acc[3][6]); acc[3][7] = fma2(y3, wg.y, acc[3][7]);
        if (chk == 0) {
            float wv64 = s_w64[c];
            u64 w64p = pack2(wv64, wv64);
            acc64a = fma2(pack2(yv.x, yv.y), w64p, acc64a);
            acc64b = fma2(pack2(yv.z, yv.w), w64p, acc64b);
        }
    }
    __syncthreads();   // all yT reads done -> stage region may be written

    // ----- stage logits + per-token LSE partials -----
    float bias64 = c_blm[64];
#pragma unroll
    for (int tt = 0; tt < 4; tt++) {
        const int tokg = tb + tt;
        float* srow = s_un + tokg * 65 + vb;
        float l[16];
#pragma unroll
        for (int p = 0; p < 8; p++) {
            l[2 * p] = lo2(acc[tt][p]); l[2 * p + 1] = hi2(acc[tt][p]);
            srow[2 * p]     = l[2 * p];
            srow[2 * p + 1] = l[2 * p + 1];
        }
        float t0 = fmaxf(l[0], l[1]),  t1 = fmaxf(l[2], l[3]);
        float t2 = fmaxf(l[4], l[5]),  t3 = fmaxf(l[6], l[7]);
        float t4 = fmaxf(l[8], l[9]),  t5 = fmaxf(l[10], l[11]);
        float t6 = fmaxf(l[12], l[13]), t7 = fmaxf(l[14], l[15]);
        float m = fmaxf(fmaxf(fmaxf(t0, t1), fmaxf(t2, t3)),
                        fmaxf(fmaxf(t4, t5), fmaxf(t6, t7)));
        float l64 = 0.f;
        if (chk == 0) {
            u64 a = (tt < 2) ? acc64a : acc64b;
            l64 = ((tt & 1) ? hi2(a) : lo2(a)) + bias64;
            s_un[tokg * 65 + 64] = l64;
            m = fmaxf(m, l64);
        }
        float e[16];
#pragma unroll
        for (int p = 0; p < 16; p++) e[p] = __expf(l[p] - m);
        float s0 = ((e[0] + e[1]) + (e[2] + e[3])) + ((e[4] + e[5]) + (e[6] + e[7]));
        float s1 = ((e[8] + e[9]) + (e[10] + e[11])) + ((e[12] + e[13]) + (e[14] + e[15]));
        float s = s0 + s1;
        if (chk == 0) s += __expf(l64 - m);
        s_part[tokg * 5 + chk] = make_float2(m, s);
    }
    __syncthreads();

    // ----- per-token combine (thread tid owns token tid), loss, flush -----
    float lossi;
    {
        float2 p0 = s_part[tid * 5 + 0];
        float2 p1 = s_part[tid * 5 + 1];
        float2 p2 = s_part[tid * 5 + 2];
        float2 p3 = s_part[tid * 5 + 3];
        float m = fmaxf(fmaxf(p0.x, p1.x), fmaxf(p2.x, p3.x));
        float s = p0.y * __expf(p0.x - m) + p1.y * __expf(p1.x - m)
                + p2.y * __expf(p2.x - m) + p3.y * __expf(p3.x - m);
        lossi = (m + __logf(s)) - s_un[tid * 65 + tgtv];
    }
#pragma unroll
    for (int off = 16; off > 0; off >>= 1)
        lossi += __shfl_down_sync(0xffffffffu, lossi, off);
    if ((tid & 31) == 0) s_lred[tid >> 5] = lossi;
    __syncthreads();
    if (tid == 0) {
        atomicAdd(&g_loss, s_lred[0] + s_lred[1] + s_lred[2] + s_lred[3]);
        __threadfence();
        unsigned prev = atomicAdd(&g_done, 1u);
        if ((int)prev == nblocks - 1 && loss_idx >= 0)
            out[loss_idx] = g_loss * inv_n;
    }

    // ----- single TMA bulk store: SMEM stage -> GMEM logits (33280 B) -----
    if (write_logits && tid == 0) {
        u32 saddr;
        asm("{ .reg .u64 tmp; cvta.to.shared.u64 tmp, %1; cvt.u32.u64 %0, tmp; }"
            : "=r"(saddr) : "l"(s_un));
        const float* gdst = out + (size_t)blockIdx.x * 8320;
        asm volatile("fence.proxy.async.shared::cta;" ::: "memory");
        asm volatile("cp.async.bulk.global.shared::cta.bulk_group [%0], [%1], %2;"
                     :: "l"(gdst), "r"(saddr), "r"(33280) : "memory");
        asm volatile("cp.async.bulk.commit_group;" ::: "memory");
        asm volatile("cp.async.bulk.wait_group.read 0;" ::: "memory");
    }
}

extern "C" void kernel_launch(void* const* d_in, const int* in_sizes, int n_in,
                              void* d_out, int out_size) {
    const int*   idx     = (const int*)d_in[0];
    const int*   targets = (const int*)d_in[1];
    const float* tok_emb = (const float*)d_in[2];
    const float* pos_emb = (const float*)d_in[3];
    const float* Wq      = (const float*)d_in[4];
    const float* Wk      = (const float*)d_in[5];
    const float* Wv      = (const float*)d_in[6];
    const float* Wmlp    = (const float*)d_in[7];
    const float* bmlp    = (const float*)d_in[8];
    const float* Wlm     = (const float*)d_in[9];
    const float* blm     = (const float*)d_in[10];
    float* out = (float*)d_out;

    const long nrows = in_sizes[0];           // B*T = 524288
    const long total = nrows * VOCAB;
    int write_logits = ((long)out_size >= total) ? 1 : 0;
    int loss_idx = -1;
    if ((long)out_size == total + 1) loss_idx = (int)total;
    else if (out_size == 1)          { loss_idx = 0; write_logits = 0; }

    int work = 520 * 32 + PACK_N;
    k_tables<<<(work + 255) / 256, 256>>>(tok_emb, pos_emb, Wq, Wk, Wv,
                                          Wmlp, bmlp, Wlm, blm);
    {
        void* src = nullptr;
        cudaGetSymbolAddress(&src, g_pack);
        cudaMemcpyToSymbolAsync(c_all, src, PACK_N * sizeof(float), 0,
                                cudaMemcpyDeviceToDevice);
    }

    int nblocks = (int)(nrows / 128);
    k_main<<<nblocks, 128>>>(idx, targets, out, write_logits, loss_idx,
                             1.0f / (float)nrows, nblocks);
}

// round 14
// speedup vs baseline: 1.4392x; 1.1912x over previous
#include <cuda_runtime.h>
#include <cuda_bf16.h>

typedef unsigned long long u64;
typedef unsigned int u32;

#define VOCAB   65
#define SQRT_C  5.656854249492381f   // faithful bug: scores MULTIPLIED by sqrt(32)

// ---------------- scratch (device globals; no allocations allowed) ----------
__device__ __align__(16) float g_Qtab[520 * 32];
__device__ __align__(16) float g_Ktab[520 * 32];   // pre-scaled by SQRT_C
__device__ __align__(16) float g_Vtab[520 * 32];
__device__ __align__(16) u32   g_bfrag[2304];      // Wlm bf16 hi/lo mma B-fragments
__device__ float    g_loss;
__device__ unsigned g_done;

// ---------------- packed weights: one constant block, one memcpy ------------
#define WLM_STRIDE 68
#define OFF_WMLP   0           // [c][c2] 1024
#define OFF_BMLP   1024        // 32
#define OFF_BLM    1056        // 68 (65 + zero pad)
#define OFF_WLM    1124        // [c][v] 32*68 = 2176
#define PACK_N     3300
__device__   __align__(16) float g_pack[PACK_N];
__constant__ __align__(16) float c_all[PACK_N];    // MLP weights + biases

// ---------------- packed f32x2 helpers (sm_103a) ----------------------------
__device__ __forceinline__ u64 fma2(u64 a, u64 b, u64 c) {
    u64 d; asm("fma.rn.f32x2 %0, %1, %2, %3;" : "=l"(d) : "l"(a), "l"(b), "l"(c)); return d;
}
__device__ __forceinline__ u64 add2(u64 a, u64 b) {
    u64 d; asm("add.rn.f32x2 %0, %1, %2;" : "=l"(d) : "l"(a), "l"(b)); return d;
}
__device__ __forceinline__ float hadd2(u64 a) {
    float lo, hi; asm("mov.b64 {%0,%1}, %2;" : "=f"(lo), "=f"(hi) : "l"(a)); return lo + hi;
}
__device__ __forceinline__ u64 pack2(float lo, float hi) {
    u64 r; asm("mov.b64 %0, {%1,%2};" : "=l"(r) : "f"(lo), "f"(hi)); return r;
}
__device__ __forceinline__ float lo2(u64 a) {
    float lo, hi; asm("mov.b64 {%0,%1}, %2;" : "=f"(lo), "=f"(hi) : "l"(a)); return lo;
}
__device__ __forceinline__ float hi2(u64 a) {
    float lo, hi; asm("mov.b64 {%0,%1}, %2;" : "=f"(lo), "=f"(hi) : "l"(a)); return hi;
}
__device__ __forceinline__ ulonglong2 ldc4(const float* p) {
    return *reinterpret_cast<const ulonglong2*>(p);
}
// m16n8k16 bf16 mma, f32 accumulate in-place
__device__ __forceinline__ void mma_bf16(float* d, const u32* a, u32 b0, u32 b1) {
    asm volatile("mma.sync.aligned.m16n8k16.row.col.f32.bf16.bf16.f32 "
                 "{%0,%1,%2,%3}, {%4,%5,%6,%7}, {%8,%9}, {%0,%1,%2,%3};"
                 : "+f"(d[0]), "+f"(d[1]), "+f"(d[2]), "+f"(d[3])
                 : "r"(a[0]), "r"(a[1]), "r"(a[2]), "r"(a[3]), "r"(b0), "r"(b1));
}

// Precompute Q/K/V tables, pack weights, and build Wlm mma B-fragments.
__global__ void k_tables(const float* __restrict__ tok_emb,
                         const float* __restrict__ pos_emb,
                         const float* __restrict__ Wq,
                         const float* __restrict__ Wk,
                         const float* __restrict__ Wv,
                         const float* __restrict__ Wmlp,
                         const float* __restrict__ bmlp,
                         const float* __restrict__ Wlm,
                         const float* __restrict__ blm) {
    int i = blockIdx.x * blockDim.x + threadIdx.x;
    if (i == 0) { g_loss = 0.0f; g_done = 0u; }
    if (i < 520 * 32) {
        int row = i >> 5, c = i & 31;
        int t = row / 65, tok = row % 65;
        int h = c >> 3, d = c & 7;
        float aq = 0.f, ak = 0.f, av = 0.f;
#pragma unroll
        for (int cc = 0; cc < 32; cc++) {
            float xv = tok_emb[tok * 32 + cc] + pos_emb[t * 32 + cc];
            int wi = h * 256 + cc * 8 + d;
            aq = fmaf(xv, Wq[wi], aq);
            ak = fmaf(xv, Wk[wi], ak);
            av = fmaf(xv, Wv[wi], av);
        }
        g_Qtab[i] = aq;
        g_Ktab[i] = ak * SQRT_C;
        g_Vtab[i] = av;
    } else if (i < 520 * 32 + PACK_N) {
        int i2 = i - 520 * 32;
        float v;
        if (i2 < OFF_BMLP)      v = Wmlp[i2];
        else if (i2 < OFF_BLM)  v = bmlp[i2 - OFF_BMLP];
        else if (i2 < OFF_WLM) {
            int j = i2 - OFF_BLM;
            v = (j < 65) ? blm[j] : 0.0f;
        } else {
            int j  = i2 - OFF_WLM;
            int c  = j / WLM_STRIDE;
            int vv = j - c * WLM_STRIDE;
            v = (vv < 65) ? Wlm[c * 65 + vv] : 0.0f;
        }
        g_pack[i2] = v;
    } else if (i < 520 * 32 + PACK_N + 2304) {
        // B-fragment for mma.m16n8k16 (row.col): lane holds
        //   b0 = {B[tig*2 + kt*16][n], B[tig*2+1 + kt*16][n]}
        //   b1 = {B[tig*2+8 + kt*16][n], B[tig*2+9 + kt*16][n]},  n = nt*8 + gid
        // layout: idx = ((nt*2 + plane)*32 + lane)*4 + kt*2 + reg
        int i3   = i - 520 * 32 - PACK_N;
        int reg  = i3 & 1;
        int kt   = (i3 >> 1) & 1;
        int lane = (i3 >> 2) & 31;
        int q    = i3 >> 7;
        int p    = q & 1;          // 0 = hi plane, 1 = lo plane
        int nt   = q >> 1;         // 0..8
        int gid  = lane >> 2, tig = lane & 3;
        int n    = nt * 8 + gid;   // vocab column
        int k0   = tig * 2 + reg * 8 + kt * 16;   // channel (contraction)
        float v0 = (n < 65) ? Wlm[k0 * 65 + n] : 0.f;
        float v1 = (n < 65) ? Wlm[(k0 + 1) * 65 + n] : 0.f;
        __nv_bfloat16 h0 = __float2bfloat16(v0), h1 = __float2bfloat16(v1);
        u32 outv;
        if (p == 0) {
            outv = (u32)__bfloat16_as_ushort(h0) | ((u32)__bfloat16_as_ushort(h1) << 16);
        } else {
            __nv_bfloat16 l0 = __float2bfloat16(v0 - __bfloat162float(h0));
            __nv_bfloat16 l1 = __float2bfloat16(v1 - __bfloat162float(h1));
            outv = (u32)__bfloat16_as_ushort(l0) | ((u32)__bfloat16_as_ushort(l1) << 16);
        }
        g_bfrag[i3] = outv;
    }
}

#define KV_LS_STRIDE 264   // floats per sequence (K/V phase)
#define YB_ROW       144   // yb row stride bytes (36 banks -> conflict-free A loads)

// Main fused kernel: 128 threads. Attention+MLP: thread = token.
// lm-head: HMMA — warp w computes logits for tokens 32w..32w+31, all 72 padded vocab.
__global__ __launch_bounds__(128, 4)
void k_main(const int* __restrict__ idx, const int* __restrict__ tgt,
            float* __restrict__ out, int write_logits,
            int loss_idx, float inv_n, int nblocks) {
    // s_un phases: K[0..4224) V[4224..8448) -> yb bf16 [0..4608 floats) -> stage [128][65]
    __shared__ __align__(16) float s_un[8448];
    __shared__ __align__(16) u32   s_bf[2304];    // B fragments (9nt x 2 planes)
    __shared__ __align__(16) float s_bias[72];
    __shared__ float               s_lred[4];

    const float* c_wmlp = c_all + OFF_WMLP;
    const float* c_bmlp = c_all + OFF_BMLP;

    const int tid  = threadIdx.x;
    const int lane = tid & 31;
    const int gid  = lane >> 2;
    const int tig  = lane & 3;
    const int wbase = (tid >> 5) * 32;         // warp's token base
    const int ls   = tid >> 3;
    const int t    = tid & 7;
    const int rowg = blockIdx.x * 128 + tid;
    const int tok  = idx[rowg];
    const int tgtv = tgt[rowg];
    const int qrow = (t * 65 + tok) * 32;

    // stage B fragments + bias
    {
        const uint4* src = reinterpret_cast<const uint4*>(g_bfrag);
        uint4*       dst = reinterpret_cast<uint4*>(s_bf);
        for (int i = tid; i < 576; i += 128) dst[i] = src[i];
    }
    if (tid < 72) s_bias[tid] = (tid < 65) ? g_pack[OFF_BLM + tid] : 0.f;

    // k, v rows into shared
    {
        const float4* k4 = reinterpret_cast<const float4*>(g_Ktab + qrow);
        const float4* v4 = reinterpret_cast<const float4*>(g_Vtab + qrow);
        float4* skd = reinterpret_cast<float4*>(s_un + ls * KV_LS_STRIDE + t * 32);
        float4* svd = reinterpret_cast<float4*>(s_un + 4224 + ls * KV_LS_STRIDE + t * 32);
#pragma unroll
        for (int j = 0; j < 8; j++) { skd[j] = k4[j]; svd[j] = v4[j]; }
    }
    __syncthreads();

    // ----- attention in head-pairs (proven R7 structure) -----
    float ov[32];
#pragma unroll
    for (int hp = 0; hp < 2; hp++) {
        u64 q2[8];
        {
            const ulonglong2* q4 =
                reinterpret_cast<const ulonglong2*>(g_Qtab + qrow + hp * 16);
#pragma unroll
            for (int j = 0; j < 4; j++) {
                ulonglong2 a = q4[j];
                q2[2 * j] = a.x; q2[2 * j + 1] = a.y;
            }
        }
        float sc[2][8];
        const float* kb = s_un + ls * KV_LS_STRIDE + hp * 16;
#pragma unroll
        for (int s = 0; s < 8; s++) {
            const ulonglong2* kr = reinterpret_cast<const ulonglong2*>(kb + s * 32);
            ulonglong2 a = kr[0], b = kr[1], c = kr[2], d = kr[3];
            u64 e0 = 0ull, e1 = 0ull, f0 = 0ull, f1 = 0ull;
            e0 = fma2(q2[0], a.x, e0); e1 = fma2(q2[1], a.y, e1);
            e0 = fma2(q2[2], b.x, e0); e1 = fma2(q2[3], b.y, e1);
            f0 = fma2(q2[4], c.x, f0); f1 = fma2(q2[5], c.y, f1);
            f0 = fma2(q2[6], d.x, f0); f1 = fma2(q2[7], d.y, f1);
            float se = hadd2(add2(e0, e1));
            float sf = hadd2(add2(f0, f1));
            sc[0][s] = (s <= t) ? se : -1e30f;
            sc[1][s] = (s <= t) ? sf : -1e30f;
        }
        float rinv[2];
#pragma unroll
        for (int hh = 0; hh < 2; hh++) {
            float m01 = fmaxf(sc[hh][0], sc[hh][1]);
            float m23 = fmaxf(sc[hh][2], sc[hh][3]);
            float m45 = fmaxf(sc[hh][4], sc[hh][5]);
            float m67 = fmaxf(sc[hh][6], sc[hh][7]);
            float m = fmaxf(fmaxf(m01, m23), fmaxf(m45, m67));
            float sum = 0.f;
#pragma unroll
            for (int s = 0; s < 8; s++) {
                float e = __expf(sc[hh][s] - m);
                sc[hh][s] = e;
                sum += e;
            }
            rinv[hh] = __fdividef(1.0f, sum);
        }
        u64 oacc[8];
#pragma unroll
        for (int j = 0; j < 8; j++) oacc[j] = 0ull;
        const float* vb = s_un + 4224 + ls * KV_LS_STRIDE + hp * 16;
#pragma unroll
        for (int s = 0; s < 8; s++) {
            const ulonglong2* vr = reinterpret_cast<const ulonglong2*>(vb + s * 32);
            ulonglong2 a = vr[0], b = vr[1], c = vr[2], d = vr[3];
            float p0 = sc[0][s] * rinv[0];
            float p1 = sc[1][s] * rinv[1];
            u64 p02 = pack2(p0, p0), p12 = pack2(p1, p1);
            oacc[0] = fma2(p02, a.x, oacc[0]); oacc[1] = fma2(p02, a.y, oacc[1]);
            oacc[2] = fma2(p02, b.x, oacc[2]); oacc[3] = fma2(p02, b.y, oacc[3]);
            oacc[4] = fma2(p12, c.x, oacc[4]); oacc[5] = fma2(p12, c.y, oacc[5]);
            oacc[6] = fma2(p12, d.x, oacc[6]); oacc[7] = fma2(p12, d.y, oacc[7]);
        }
#pragma unroll
        for (int j = 0; j < 8; j++) {
            ov[hp * 16 + 2 * j]     = lo2(oacc[j]);
            ov[hp * 16 + 2 * j + 1] = hi2(oacc[j]);
        }
    }
    __syncthreads();   // all K/V reads done -> s_un reusable

    // ----- MLP (CONSTANT port) -----
    u64 macc[16];
#pragma unroll
    for (int j = 0; j < 8; j++) {
        ulonglong2 b = ldc4(c_bmlp + 4 * j);
        macc[2 * j] = b.x; macc[2 * j + 1] = b.y;
    }
#pragma unroll
    for (int c = 0; c < 32; c++) {
        u64 xb = pack2(ov[c], ov[c]);
#pragma unroll
        for (int jj = 0; jj < 8; jj++) {
            ulonglong2 w = ldc4(c_wmlp + c * 32 + 4 * jj);
            macc[2 * jj]     = fma2(xb, w.x, macc[2 * jj]);
            macc[2 * jj + 1] = fma2(xb, w.y, macc[2 * jj + 1]);
        }
    }

    // ----- y -> bf16 hi/lo planes in smem: yb[token][hi 32 | lo 32] bf16 -----
    char* ybb = reinterpret_cast<char*>(s_un);
#pragma unroll
    for (int j = 0; j < 16; j++) {
        float y0 = fmaxf(lo2(macc[j]), 0.f);
        float y1 = fmaxf(hi2(macc[j]), 0.f);
        u32 hp;
        asm("cvt.rn.bf16x2.f32 %0, %1, %2;" : "=r"(hp) : "f"(y1), "f"(y0));
        float l0 = y0 - __uint_as_float(hp << 16);
        float l1 = y1 - __uint_as_float(hp & 0xffff0000u);
        u32 lp;
        asm("cvt.rn.bf16x2.f32 %0, %1, %2;" : "=r"(lp) : "f"(l1), "f"(l0));
        *reinterpret_cast<u32*>(ybb + tid * YB_ROW + j * 4)      = hp;
        *reinterpret_cast<u32*>(ybb + tid * YB_ROW + 64 + j * 4) = lp;
    }
    __syncthreads();

    // ----- load A fragments: af[mt][plane][kt][4] -----
    u32 af[2][2][2][4];
#pragma unroll
    for (int mt = 0; mt < 2; mt++)
#pragma unroll
        for (int p = 0; p < 2; p++)
#pragma unroll
            for (int kt = 0; kt < 2; kt++) {
                int r0   = (wbase + mt * 16 + gid) * YB_ROW;
                int colb = p * 64 + kt * 32 + tig * 4;
                af[mt][p][kt][0] = *reinterpret_cast<const u32*>(ybb + r0 + colb);
                af[mt][p][kt][1] = *reinterpret_cast<const u32*>(ybb + r0 + 8 * YB_ROW + colb);
                af[mt][p][kt][2] = *reinterpret_cast<const u32*>(ybb + r0 + colb + 16);
                af[mt][p][kt][3] = *reinterpret_cast<const u32*>(ybb + r0 + 8 * YB_ROW + colb + 16);
            }
    __syncthreads();   // all A frags in regs -> stage region writable

    // ----- mma passes over 9 n-tiles (vocab 0..71, zero-padded >= 65) -----
    float acc[2][5][4];
#define MMA_PASS(NTS, CNT)                                                     \
    {                                                                          \
        _Pragma("unroll")                                                      \
        for (int nn = 0; nn < (CNT); nn++) {                                   \
            int v0 = ((NTS) + nn) * 8 + tig * 2;                               \
            float b0 = s_bias[v0], b1 = s_bias[v0 + 1];                        \
            _Pragma("unroll")                                                  \
            for (int mt = 0; mt < 2; mt++) {                                   \
                acc[mt][nn][0] = b0; acc[mt][nn][1] = b1;                      \
                acc[mt][nn][2] = b0; acc[mt][nn][3] = b1;                      \
            }                                                                  \
        }                                                                      \
        _Pragma("unroll")                                                      \
        for (int nn = 0; nn < (CNT); nn++) {                                   \
            int nt = (NTS) + nn;                                               \
            uint4 bh = *reinterpret_cast<const uint4*>(s_bf + (nt * 2 + 0) * 128 + lane * 4); \
            uint4 bl = *reinterpret_cast<const uint4*>(s_bf + (nt * 2 + 1) * 128 + lane * 4); \
            _Pragma("unroll")                                                  \
            for (int mt = 0; mt < 2; mt++) {                                   \
                mma_bf16(acc[mt][nn], af[mt][0][0], bh.x, bh.y);               \
                mma_bf16(acc[mt][nn], af[mt][0][1], bh.z, bh.w);               \
                mma_bf16(acc[mt][nn], af[mt][1][0], bh.x, bh.y);               \
                mma_bf16(acc[mt][nn], af[mt][1][1], bh.z, bh.w);               \
                mma_bf16(acc[mt][nn], af[mt][0][0], bl.x, bl.y);               \
                mma_bf16(acc[mt][nn], af[mt][0][1], bl.z, bl.w);               \
            }                                                                  \
        }                                                                      \
        _Pragma("unroll")                                                      \
        for (int nn = 0; nn < (CNT); nn++) {                                   \
            int v0 = ((NTS) + nn) * 8 + tig * 2;                               \
            _Pragma("unroll")                                                  \
            for (int mt = 0; mt < 2; mt++) {                                   \
                int r0 = wbase + mt * 16 + gid;                                \
                if (v0 < 65) {                                                 \
                    s_un[r0 * 65 + v0]       = acc[mt][nn][0];                 \
                    s_un[(r0 + 8) * 65 + v0] = acc[mt][nn][2];                 \
                }                                                              \
                if (v0 + 1 < 65) {                                             \
                    s_un[r0 * 65 + v0 + 1]       = acc[mt][nn][1];             \
                    s_un[(r0 + 8) * 65 + v0 + 1] = acc[mt][nn][3];             \
                }                                                              \
            }                                                                  \
        }                                                                      \
    }
    MMA_PASS(0, 5)
    MMA_PASS(5, 4)
#undef MMA_PASS
    __syncthreads();   // stage complete

    // ----- LSE over own token's staged row (SCALAR loads: stride-65 rows are
    //       only 4B-aligned; lane bank = tid%32 so reads are conflict-free) ---
    const float* srow = s_un + tid * 65;
    float m = -1e30f, sum = 0.f;
#pragma unroll
    for (int chunk = 0; chunk < 4; chunk++) {
        float l[16];
#pragma unroll
        for (int p = 0; p < 16; p++) l[p] = srow[chunk * 16 + p];
        float t0 = fmaxf(l[0], l[1]),  t1 = fmaxf(l[2], l[3]);
        float t2 = fmaxf(l[4], l[5]),  t3 = fmaxf(l[6], l[7]);
        float t4 = fmaxf(l[8], l[9]),  t5 = fmaxf(l[10], l[11]);
        float t6 = fmaxf(l[12], l[13]), t7 = fmaxf(l[14], l[15]);
        float cm = fmaxf(fmaxf(fmaxf(t0, t1), fmaxf(t2, t3)),
                         fmaxf(fmaxf(t4, t5), fmaxf(t6, t7)));
        float mn = fmaxf(m, cm);
        float e[16];
#pragma unroll
        for (int p = 0; p < 16; p++) e[p] = __expf(l[p] - mn);
        float s0 = ((e[0] + e[1]) + (e[2] + e[3])) + ((e[4] + e[5]) + (e[6] + e[7]));
        float s1 = ((e[8] + e[9]) + (e[10] + e[11])) + ((e[12] + e[13]) + (e[14] + e[15]));
        sum = sum * __expf(m - mn) + (s0 + s1);
        m = mn;
    }
    {
        float l64 = srow[64];
        float mn = fmaxf(m, l64);
        sum = sum * __expf(m - mn) + __expf(l64 - mn);
        m = mn;
    }
    float lossi = (m + __logf(sum)) - srow[tgtv];

    // warp then block reduce; last block writes mean
#pragma unroll
    for (int off = 16; off > 0; off >>= 1)
        lossi += __shfl_down_sync(0xffffffffu, lossi, off);
    if ((tid & 31) == 0) s_lred[tid >> 5] = lossi;
    __syncthreads();
    if (tid == 0) {
        atomicAdd(&g_loss, s_lred[0] + s_lred[1] + s_lred[2] + s_lred[3]);
        __threadfence();
        unsigned prev = atomicAdd(&g_done, 1u);
        if ((int)prev == nblocks - 1 && loss_idx >= 0)
            out[loss_idx] = g_loss * inv_n;
    }

    // ----- single TMA bulk store: stage -> GMEM logits -----
    if (write_logits && tid == 0) {
        u32 saddr;
        asm("{ .reg .u64 tmp; cvta.to.shared.u64 tmp, %1; cvt.u32.u64 %0, tmp; }"
            : "=r"(saddr) : "l"(s_un));
        const float* gdst = out + (size_t)blockIdx.x * 8320;
        asm volatile("fence.proxy.async.shared::cta;" ::: "memory");
        asm volatile("cp.async.bulk.global.shared::cta.bulk_group [%0], [%1], %2;"
                     :: "l"(gdst), "r"(saddr), "r"(33280) : "memory");
        asm volatile("cp.async.bulk.commit_group;" ::: "memory");
        asm volatile("cp.async.bulk.wait_group.read 0;" ::: "memory");
    }
}

extern "C" void kernel_launch(void* const* d_in, const int* in_sizes, int n_in,
                              void* d_out, int out_size) {
    const int*   idx     = (const int*)d_in[0];
    const int*   targets = (const int*)d_in[1];
    const float* tok_emb = (const float*)d_in[2];
    const float* pos_emb = (const float*)d_in[3];
    const float* Wq      = (const float*)d_in[4];
    const float* Wk      = (const float*)d_in[5];
    const float* Wv      = (const float*)d_in[6];
    const float* Wmlp    = (const float*)d_in[7];
    const float* bmlp    = (const float*)d_in[8];
    const float* Wlm     = (const float*)d_in[9];
    const float* blm     = (const float*)d_in[10];
    float* out = (float*)d_out;

    const long nrows = in_sizes[0];           // B*T = 524288
    const long total = nrows * VOCAB;
    int write_logits = ((long)out_size >= total) ? 1 : 0;
    int loss_idx = -1;
    if ((long)out_size == total + 1) loss_idx = (int)total;
    else if (out_size == 1)          { loss_idx = 0; write_logits = 0; }

    int work = 520 * 32 + PACK_N + 2304;
    k_tables<<<(work + 255) / 256, 256>>>(tok_emb, pos_emb, Wq, Wk, Wv,
                                          Wmlp, bmlp, Wlm, blm);
    {
        void* src = nullptr;
        cudaGetSymbolAddress(&src, g_pack);
        cudaMemcpyToSymbolAsync(c_all, src, PACK_N * sizeof(float), 0,
                                cudaMemcpyDeviceToDevice);
    }

    int nblocks = (int)(nrows / 128);
    k_main<<<nblocks, 128>>>(idx, targets, out, write_logits, loss_idx,
                             1.0f / (float)nrows, nblocks);
}